// round 8
// baseline (speedup 1.0000x reference)
#include <cuda_runtime.h>
#include <cuda_fp16.h>
#include <cstdint>

// ---------------------------------------------------------------------------
// Problem constants
// ---------------------------------------------------------------------------
#define BS      2
#define SEQ     4096
#define DMODEL  768
#define HEADS   12
#define DK      64
#define MROWS   (BS * SEQ)          // 8192

// ---------------------------------------------------------------------------
// Scratch (device globals; no cudaMalloc allowed)
// ---------------------------------------------------------------------------
__device__ __half g_Qp[MROWS * DMODEL];              // prescaled by 1/8
__device__ __half g_Kp[MROWS * DMODEL];
__device__ __half g_Vt[(size_t)BS * DMODEL * SEQ];   // [b][dmodel][seq]
__device__ float  g_Ctx[MROWS * DMODEL];

// ---------------------------------------------------------------------------
// Helpers
// ---------------------------------------------------------------------------
__device__ __forceinline__ void mma16(float* d, const uint32_t* a,
                                      uint32_t b0, uint32_t b1) {
    asm volatile(
        "mma.sync.aligned.m16n8k16.row.col.f32.f16.f16.f32 "
        "{%0,%1,%2,%3}, {%4,%5,%6,%7}, {%8,%9}, {%0,%1,%2,%3};"
        : "+f"(d[0]), "+f"(d[1]), "+f"(d[2]), "+f"(d[3])
        : "r"(a[0]), "r"(a[1]), "r"(a[2]), "r"(a[3]), "r"(b0), "r"(b1));
}

__device__ __forceinline__ uint32_t packh2(float a, float b) {
    __half2 h = __floats2half2_rn(a, b);
    return *(uint32_t*)&h;
}

__device__ __forceinline__ void st_h4(__half* p, float4 v) {
    uint2 u;
    u.x = packh2(v.x, v.y);
    u.y = packh2(v.z, v.w);
    *(uint2*)p = u;
}

__device__ __forceinline__ void cpa16(void* dst, const void* src) {
    uint32_t d = (uint32_t)__cvta_generic_to_shared(dst);
    asm volatile("cp.async.cg.shared.global [%0], [%1], 16;"
                 :: "r"(d), "l"(src));
}
#define CPA_COMMIT() asm volatile("cp.async.commit_group;" ::: "memory")
#define CPA_WAIT1()  asm volatile("cp.async.wait_group 1;" ::: "memory")
#define CPA_WAIT0()  asm volatile("cp.async.wait_group 0;" ::: "memory")

// ---------------------------------------------------------------------------
// GEMM: C[M,N] = (A[M,K] @ B[N,K]^T + bias[N]) * scale  (round-7 proven)
// ---------------------------------------------------------------------------
#define GBM 128
#define GBN 128
#define GBK 32
#define GLDH 40

template <typename OutT, int TRANS>
__global__ __launch_bounds__(256, 2) void gemm_tc(
    const float* __restrict__ A, const float* __restrict__ B,
    const float* __restrict__ bias, OutT* __restrict__ C,
    int M, int N, int K, float scale)
{
    __shared__ __half As[GBM * GLDH];
    __shared__ __half Bs[GBN * GLDH];

    const int tid = threadIdx.x;
    const int lane = tid & 31, wid = tid >> 5;
    const int g = lane >> 2, tig = lane & 3;
    const int wm = (wid & 3) * 32, wn = (wid >> 2) * 64;
    const int row0 = blockIdx.y * GBM, col0 = blockIdx.x * GBN;

    const int r = tid >> 3;
    const int c4 = (tid & 7) * 4;
    const float* Aptr = A + (size_t)(row0 + r) * K + c4;
    const float* Bptr = B + (size_t)(col0 + r) * K + c4;

    float4 pa[4], pb[4];
    #pragma unroll
    for (int m = 0; m < 4; m++) {
        pa[m] = *(const float4*)(Aptr + (size_t)(32 * m) * K);
        pb[m] = *(const float4*)(Bptr + (size_t)(32 * m) * K);
    }

    float acc[2][8][4] = {};

    int k0 = 0;
    while (true) {
        __syncthreads();
        #pragma unroll
        for (int m = 0; m < 4; m++) {
            st_h4(As + (r + 32 * m) * GLDH + c4, pa[m]);
            st_h4(Bs + (r + 32 * m) * GLDH + c4, pb[m]);
        }
        __syncthreads();

        k0 += GBK;
        const bool more = (k0 < K);
        if (more) {
            #pragma unroll
            for (int m = 0; m < 4; m++) {
                pa[m] = *(const float4*)(Aptr + (size_t)(32 * m) * K + k0);
                pb[m] = *(const float4*)(Bptr + (size_t)(32 * m) * K + k0);
            }
        }

        #pragma unroll
        for (int c = 0; c < 2; c++) {
            const int kk = 16 * c + 2 * tig;
            uint32_t a[2][4];
            #pragma unroll
            for (int i = 0; i < 2; i++) {
                const int rb = wm + 16 * i;
                a[i][0] = *(const uint32_t*)&As[(rb + g) * GLDH + kk];
                a[i][1] = *(const uint32_t*)&As[(rb + 8 + g) * GLDH + kk];
                a[i][2] = *(const uint32_t*)&As[(rb + g) * GLDH + kk + 8];
                a[i][3] = *(const uint32_t*)&As[(rb + 8 + g) * GLDH + kk + 8];
            }
            #pragma unroll
            for (int j = 0; j < 8; j++) {
                const int cn = wn + j * 8 + g;
                uint32_t b0 = *(const uint32_t*)&Bs[cn * GLDH + kk];
                uint32_t b1 = *(const uint32_t*)&Bs[cn * GLDH + kk + 8];
                mma16(acc[0][j], a[0], b0, b1);
                mma16(acc[1][j], a[1], b0, b1);
            }
        }
        if (!more) break;
    }

    #pragma unroll
    for (int i = 0; i < 2; i++) {
        const int rA = row0 + wm + i * 16 + g;
        const int rB = rA + 8;
        #pragma unroll
        for (int j = 0; j < 8; j++) {
            const int col = col0 + wn + j * 8 + 2 * tig;
            const float bx = __ldg(bias + col), by = __ldg(bias + col + 1);
            const float v0 = (acc[i][j][0] + bx) * scale;
            const float v1 = (acc[i][j][1] + by) * scale;
            const float v2 = (acc[i][j][2] + bx) * scale;
            const float v3 = (acc[i][j][3] + by) * scale;
            if (TRANS == 0) {
                if (sizeof(OutT) == 2) {
                    __half2* pA = (__half2*)((__half*)C + (size_t)rA * N + col);
                    __half2* pB = (__half2*)((__half*)C + (size_t)rB * N + col);
                    *pA = __floats2half2_rn(v0, v1);
                    *pB = __floats2half2_rn(v2, v3);
                } else {
                    *(float2*)((float*)C + (size_t)rA * N + col) = make_float2(v0, v1);
                    *(float2*)((float*)C + (size_t)rB * N + col) = make_float2(v2, v3);
                }
            } else {
                const int bA = rA >> 12, sA = rA & (SEQ - 1);
                const int bB = rB >> 12, sB = rB & (SEQ - 1);
                C[((size_t)bA * DMODEL + col)     * SEQ + sA] = (OutT)v0;
                C[((size_t)bA * DMODEL + col + 1) * SEQ + sA] = (OutT)v1;
                C[((size_t)bB * DMODEL + col)     * SEQ + sB] = (OutT)v2;
                C[((size_t)bB * DMODEL + col + 1) * SEQ + sB] = (OutT)v3;
            }
        }
    }
}

// ---------------------------------------------------------------------------
// Attention: fp16 mma, 32-query warp tiles, cp.async double-buffered K/V.
// CTA = (b, h, 128-query tile), 128 threads = 4 warps x 32 q-rows.
// Buffers: KV[2][128*KLD] halves -> per buffer: Ks rows 0..63, Vs rows 64..127.
// Q staged once through KV[0]; P stays in registers (C-frag == A-frag layout).
// ---------------------------------------------------------------------------
#define KLD 72
#define NT  (SEQ / 64)

__global__ void __launch_bounds__(128, 3)
attn_tc(const __half* __restrict__ Qp, const __half* __restrict__ Kp,
        const __half* __restrict__ Vt, const int* __restrict__ mask,
        float* __restrict__ Ctx)
{
    __shared__ __half KV[2][128 * KLD];
    __shared__ int Msi[2][64];

    const int tid = threadIdx.x;
    const int lane = tid & 31, wid = tid >> 5;
    const int g = lane >> 2, tig = lane & 3;
    const int b = blockIdx.y / HEADS, h = blockIdx.y % HEADS;
    const int q0 = blockIdx.x * 128;
    const int qb = wid * 32;

    const __half* kg = Kp + ((size_t)b * SEQ) * DMODEL + h * DK;
    const __half* vg = Vt + ((size_t)(b * DMODEL + h * DK)) * SEQ;
    const int* mg = mask + b * SEQ;

    // ---- stage Q (fp16, pre-scaled) through KV[0], lift A-frags ----
    {
        const __half* qg = Qp + ((size_t)(b * SEQ + q0)) * DMODEL + h * DK;
        #pragma unroll
        for (int i = 0; i < 8; i++) {
            const int L = tid + i * 128;
            const int r = L >> 3, c8 = (L & 7) * 8;
            *(uint4*)(KV[0] + r * KLD + c8) =
                *(const uint4*)(qg + (size_t)r * DMODEL + c8);
        }
    }
    __syncthreads();

    uint32_t qf[4][2][4];
    #pragma unroll
    for (int c = 0; c < 4; c++) {
        const int kk = 16 * c + 2 * tig;
        #pragma unroll
        for (int i = 0; i < 2; i++) {
            const int rb = qb + 16 * i;
            qf[c][i][0] = *(const uint32_t*)&KV[0][(rb + g) * KLD + kk];
            qf[c][i][1] = *(const uint32_t*)&KV[0][(rb + 8 + g) * KLD + kk];
            qf[c][i][2] = *(const uint32_t*)&KV[0][(rb + g) * KLD + kk + 8];
            qf[c][i][3] = *(const uint32_t*)&KV[0][(rb + 8 + g) * KLD + kk + 8];
        }
    }
    __syncthreads();

    float o[2][8][4] = {};
    float l00 = 0.f, l01 = 0.f, l10 = 0.f, l11 = 0.f;

    // prefetch tile 0 into buffer 0
    {
        #pragma unroll
        for (int i = 0; i < 4; i++) {
            const int L = tid + i * 128;
            const int r = L >> 3, c8 = (L & 7) * 8;
            cpa16(KV[0] + r * KLD + c8, kg + (size_t)r * DMODEL + c8);
            cpa16(KV[0] + (64 + r) * KLD + c8, vg + (size_t)r * SEQ + c8);
        }
        if (tid < 16) cpa16(&Msi[0][tid * 4], mg + tid * 4);
        CPA_COMMIT();
    }

    for (int kt = 0; kt < NT; kt++) {
        const int cur = kt & 1;
        const __half* Ks = KV[cur];
        const __half* Vs = KV[cur] + 64 * KLD;

        if (kt + 1 < NT) {
            // prefetch tile kt+1 into the other buffer (freed by the trailing
            // __syncthreads of iteration kt-1)
            const int nk0 = (kt + 1) * 64;
            __half* nb = KV[cur ^ 1];
            #pragma unroll
            for (int i = 0; i < 4; i++) {
                const int L = tid + i * 128;
                const int r = L >> 3, c8 = (L & 7) * 8;
                cpa16(nb + r * KLD + c8,
                      kg + (size_t)(nk0 + r) * DMODEL + c8);
                cpa16(nb + (64 + r) * KLD + c8,
                      vg + (size_t)r * SEQ + nk0 + c8);
            }
            if (tid < 16) cpa16(&Msi[cur ^ 1][tid * 4], mg + nk0 + tid * 4);
            CPA_COMMIT();
            CPA_WAIT1();            // tile kt complete, kt+1 in flight
        } else {
            CPA_WAIT0();
        }
        __syncthreads();            // staged data visible to all warps

        // ---- S = Q K^T ----
        float s[2][8][4] = {};
        #pragma unroll
        for (int c = 0; c < 4; c++) {
            const int kk = 16 * c + 2 * tig;
            #pragma unroll
            for (int j = 0; j < 8; j++) {
                const int rn = (j * 8 + g) * KLD + kk;
                uint32_t b0 = *(const uint32_t*)&Ks[rn];
                uint32_t b1 = *(const uint32_t*)&Ks[rn + 8];
                mma16(s[0][j], qf[c][0], b0, b1);
                mma16(s[1][j], qf[c][1], b0, b1);
            }
        }

        // ---- softmax; repack P in registers as O-mma A-fragments ----
        uint32_t pa[2][8][2];
        #pragma unroll
        for (int j = 0; j < 8; j++) {
            int2 mi = *(const int2*)&Msi[cur][j * 8 + 2 * tig];
            {
                float p0 = mi.x ? __expf(s[0][j][0]) : 0.f;
                float p1 = mi.y ? __expf(s[0][j][1]) : 0.f;
                float p2 = mi.x ? __expf(s[0][j][2]) : 0.f;
                float p3 = mi.y ? __expf(s[0][j][3]) : 0.f;
                l00 += p0 + p1; l01 += p2 + p3;
                pa[0][j][0] = packh2(p0, p1);
                pa[0][j][1] = packh2(p2, p3);
            }
            {
                float p0 = mi.x ? __expf(s[1][j][0]) : 0.f;
                float p1 = mi.y ? __expf(s[1][j][1]) : 0.f;
                float p2 = mi.x ? __expf(s[1][j][2]) : 0.f;
                float p3 = mi.y ? __expf(s[1][j][3]) : 0.f;
                l10 += p0 + p1; l11 += p2 + p3;
                pa[1][j][0] = packh2(p0, p1);
                pa[1][j][1] = packh2(p2, p3);
            }
        }

        // ---- O += P V^T ----
        #pragma unroll
        for (int m = 0; m < 4; m++) {
            uint32_t av0[4] = { pa[0][2 * m][0], pa[0][2 * m][1],
                                pa[0][2 * m + 1][0], pa[0][2 * m + 1][1] };
            uint32_t av1[4] = { pa[1][2 * m][0], pa[1][2 * m][1],
                                pa[1][2 * m + 1][0], pa[1][2 * m + 1][1] };
            const int kk = 16 * m + 2 * tig;
            #pragma unroll
            for (int j = 0; j < 8; j++) {
                const int rn = (j * 8 + g) * KLD + kk;
                uint32_t b0 = *(const uint32_t*)&Vs[rn];
                uint32_t b1 = *(const uint32_t*)&Vs[rn + 8];
                mma16(o[0][j], av0, b0, b1);
                mma16(o[1][j], av1, b0, b1);
            }
        }
        __syncthreads();            // protect buffer cur^1 before next prefetch
    }

    // ---- finalize ----
    l00 += __shfl_xor_sync(0xffffffffu, l00, 1);
    l00 += __shfl_xor_sync(0xffffffffu, l00, 2);
    l01 += __shfl_xor_sync(0xffffffffu, l01, 1);
    l01 += __shfl_xor_sync(0xffffffffu, l01, 2);
    l10 += __shfl_xor_sync(0xffffffffu, l10, 1);
    l10 += __shfl_xor_sync(0xffffffffu, l10, 2);
    l11 += __shfl_xor_sync(0xffffffffu, l11, 1);
    l11 += __shfl_xor_sync(0xffffffffu, l11, 2);
    const float inv[2][2] = { {1.f / l00, 1.f / l01}, {1.f / l10, 1.f / l11} };

    #pragma unroll
    for (int i = 0; i < 2; i++) {
        float* cg = Ctx + ((size_t)(b * SEQ + q0 + qb + 16 * i)) * DMODEL + h * DK;
        #pragma unroll
        for (int j = 0; j < 8; j++) {
            const int col = j * 8 + 2 * tig;
            *(float2*)(cg + (size_t)g * DMODEL + col) =
                make_float2(o[i][j][0] * inv[i][0], o[i][j][1] * inv[i][0]);
            *(float2*)(cg + (size_t)(8 + g) * DMODEL + col) =
                make_float2(o[i][j][2] * inv[i][1], o[i][j][3] * inv[i][1]);
        }
    }
}

// ---------------------------------------------------------------------------
// Launcher.  Inputs: q, k, v, Wq, bq, Wk, bk, Wv, bv, Wo, bo, mask
// ---------------------------------------------------------------------------
extern "C" void kernel_launch(void* const* d_in, const int* in_sizes, int n_in,
                              void* d_out, int out_size)
{
    const float* q    = (const float*)d_in[0];
    const float* k    = (const float*)d_in[1];
    const float* v    = (const float*)d_in[2];
    const float* Wq   = (const float*)d_in[3];
    const float* bq   = (const float*)d_in[4];
    const float* Wk   = (const float*)d_in[5];
    const float* bk   = (const float*)d_in[6];
    const float* Wv   = (const float*)d_in[7];
    const float* bv   = (const float*)d_in[8];
    const float* Wo   = (const float*)d_in[9];
    const float* bo   = (const float*)d_in[10];
    const int*   mask = (const int*)d_in[11];
    float* out = (float*)d_out;

    __half *Qp, *Kp, *Vt;
    float *Ctx;
    cudaGetSymbolAddress((void**)&Qp,  g_Qp);
    cudaGetSymbolAddress((void**)&Kp,  g_Kp);
    cudaGetSymbolAddress((void**)&Vt,  g_Vt);
    cudaGetSymbolAddress((void**)&Ctx, g_Ctx);

    dim3 ggrid(DMODEL / GBN, MROWS / GBM);   // (6, 64)
    dim3 gblk(256);

    gemm_tc<__half, 0><<<ggrid, gblk>>>(q, Wq, bq, Qp, MROWS, DMODEL, DMODEL, 0.125f);
    gemm_tc<__half, 0><<<ggrid, gblk>>>(k, Wk, bk, Kp, MROWS, DMODEL, DMODEL, 1.0f);
    gemm_tc<__half, 1><<<ggrid, gblk>>>(v, Wv, bv, Vt, MROWS, DMODEL, DMODEL, 1.0f);

    dim3 agrid(SEQ / 128, BS * HEADS);       // (32, 24)
    attn_tc<<<agrid, 128>>>(Qp, Kp, Vt, mask, Ctx);

    gemm_tc<float, 0><<<ggrid, gblk>>>(Ctx, Wo, bo, out, MROWS, DMODEL, DMODEL, 1.0f);
}

// round 9
// speedup vs baseline: 1.0991x; 1.0991x over previous
#include <cuda_runtime.h>
#include <cuda_fp16.h>
#include <cstdint>

// ---------------------------------------------------------------------------
// Problem constants
// ---------------------------------------------------------------------------
#define BS      2
#define SEQ     4096
#define DMODEL  768
#define HEADS   12
#define DK      64
#define MROWS   (BS * SEQ)          // 8192

// ---------------------------------------------------------------------------
// Scratch (device globals; no cudaMalloc allowed)
// ---------------------------------------------------------------------------
__device__ __half g_Qp[MROWS * DMODEL];              // prescaled by 1/8
__device__ __half g_Kp[MROWS * DMODEL];
__device__ __half g_Vt[(size_t)BS * DMODEL * SEQ];   // [b][dmodel][seq]
__device__ float  g_Ctx[MROWS * DMODEL];

// ---------------------------------------------------------------------------
// Helpers
// ---------------------------------------------------------------------------
__device__ __forceinline__ void mma16(float* d, const uint32_t* a,
                                      uint32_t b0, uint32_t b1) {
    asm volatile(
        "mma.sync.aligned.m16n8k16.row.col.f32.f16.f16.f32 "
        "{%0,%1,%2,%3}, {%4,%5,%6,%7}, {%8,%9}, {%0,%1,%2,%3};"
        : "+f"(d[0]), "+f"(d[1]), "+f"(d[2]), "+f"(d[3])
        : "r"(a[0]), "r"(a[1]), "r"(a[2]), "r"(a[3]), "r"(b0), "r"(b1));
}

__device__ __forceinline__ uint32_t packh2(float a, float b) {
    __half2 h = __floats2half2_rn(a, b);
    return *(uint32_t*)&h;
}

__device__ __forceinline__ void st_h4(__half* p, float4 v) {
    uint2 u;
    u.x = packh2(v.x, v.y);
    u.y = packh2(v.z, v.w);
    *(uint2*)p = u;
}

// cp.async with precomputed shared-address (uint32) destination
__device__ __forceinline__ void cpa16r(uint32_t dst, const void* src) {
    asm volatile("cp.async.cg.shared.global [%0], [%1], 16;"
                 :: "r"(dst), "l"(src));
}
#define CPA_COMMIT() asm volatile("cp.async.commit_group;" ::: "memory")
#define CPA_WAIT1()  asm volatile("cp.async.wait_group 1;" ::: "memory")
#define CPA_WAIT0()  asm volatile("cp.async.wait_group 0;" ::: "memory")

// ---------------------------------------------------------------------------
// GEMM: C[M,N] = (A[M,K] @ B[N,K]^T + bias[N]) * scale  (round-7/8 proven)
// ---------------------------------------------------------------------------
#define GBM 128
#define GBN 128
#define GBK 32
#define GLDH 40

template <typename OutT, int TRANS>
__global__ __launch_bounds__(256, 2) void gemm_tc(
    const float* __restrict__ A, const float* __restrict__ B,
    const float* __restrict__ bias, OutT* __restrict__ C,
    int M, int N, int K, float scale)
{
    __shared__ __half As[GBM * GLDH];
    __shared__ __half Bs[GBN * GLDH];

    const int tid = threadIdx.x;
    const int lane = tid & 31, wid = tid >> 5;
    const int g = lane >> 2, tig = lane & 3;
    const int wm = (wid & 3) * 32, wn = (wid >> 2) * 64;
    const int row0 = blockIdx.y * GBM, col0 = blockIdx.x * GBN;

    const int r = tid >> 3;
    const int c4 = (tid & 7) * 4;
    const float* Aptr = A + (size_t)(row0 + r) * K + c4;
    const float* Bptr = B + (size_t)(col0 + r) * K + c4;

    float4 pa[4], pb[4];
    #pragma unroll
    for (int m = 0; m < 4; m++) {
        pa[m] = *(const float4*)(Aptr + (size_t)(32 * m) * K);
        pb[m] = *(const float4*)(Bptr + (size_t)(32 * m) * K);
    }

    float acc[2][8][4] = {};

    int k0 = 0;
    while (true) {
        __syncthreads();
        #pragma unroll
        for (int m = 0; m < 4; m++) {
            st_h4(As + (r + 32 * m) * GLDH + c4, pa[m]);
            st_h4(Bs + (r + 32 * m) * GLDH + c4, pb[m]);
        }
        __syncthreads();

        k0 += GBK;
        const bool more = (k0 < K);
        if (more) {
            #pragma unroll
            for (int m = 0; m < 4; m++) {
                pa[m] = *(const float4*)(Aptr + (size_t)(32 * m) * K + k0);
                pb[m] = *(const float4*)(Bptr + (size_t)(32 * m) * K + k0);
            }
        }

        #pragma unroll
        for (int c = 0; c < 2; c++) {
            const int kk = 16 * c + 2 * tig;
            uint32_t a[2][4];
            #pragma unroll
            for (int i = 0; i < 2; i++) {
                const int rb = wm + 16 * i;
                a[i][0] = *(const uint32_t*)&As[(rb + g) * GLDH + kk];
                a[i][1] = *(const uint32_t*)&As[(rb + 8 + g) * GLDH + kk];
                a[i][2] = *(const uint32_t*)&As[(rb + g) * GLDH + kk + 8];
                a[i][3] = *(const uint32_t*)&As[(rb + 8 + g) * GLDH + kk + 8];
            }
            #pragma unroll
            for (int j = 0; j < 8; j++) {
                const int cn = wn + j * 8 + g;
                uint32_t b0 = *(const uint32_t*)&Bs[cn * GLDH + kk];
                uint32_t b1 = *(const uint32_t*)&Bs[cn * GLDH + kk + 8];
                mma16(acc[0][j], a[0], b0, b1);
                mma16(acc[1][j], a[1], b0, b1);
            }
        }
        if (!more) break;
    }

    #pragma unroll
    for (int i = 0; i < 2; i++) {
        const int rA = row0 + wm + i * 16 + g;
        const int rB = rA + 8;
        #pragma unroll
        for (int j = 0; j < 8; j++) {
            const int col = col0 + wn + j * 8 + 2 * tig;
            const float bx = __ldg(bias + col), by = __ldg(bias + col + 1);
            const float v0 = (acc[i][j][0] + bx) * scale;
            const float v1 = (acc[i][j][1] + by) * scale;
            const float v2 = (acc[i][j][2] + bx) * scale;
            const float v3 = (acc[i][j][3] + by) * scale;
            if (TRANS == 0) {
                if (sizeof(OutT) == 2) {
                    __half2* pA = (__half2*)((__half*)C + (size_t)rA * N + col);
                    __half2* pB = (__half2*)((__half*)C + (size_t)rB * N + col);
                    *pA = __floats2half2_rn(v0, v1);
                    *pB = __floats2half2_rn(v2, v3);
                } else {
                    *(float2*)((float*)C + (size_t)rA * N + col) = make_float2(v0, v1);
                    *(float2*)((float*)C + (size_t)rB * N + col) = make_float2(v2, v3);
                }
            } else {
                const int bA = rA >> 12, sA = rA & (SEQ - 1);
                const int bB = rB >> 12, sB = rB & (SEQ - 1);
                C[((size_t)bA * DMODEL + col)     * SEQ + sA] = (OutT)v0;
                C[((size_t)bA * DMODEL + col + 1) * SEQ + sA] = (OutT)v1;
                C[((size_t)bB * DMODEL + col)     * SEQ + sB] = (OutT)v2;
                C[((size_t)bB * DMODEL + col + 1) * SEQ + sB] = (OutT)v3;
            }
        }
    }
}

// ---------------------------------------------------------------------------
// Attention: fp16 mma, 32-q warp tiles, cp.async double-buffer with hoisted
// addresses, mask handled by bar.red.and fast path.
// CTA = (b, h, 128-query tile), 128 threads = 4 warps x 32 q-rows.
// ---------------------------------------------------------------------------
#define KLD 72
#define NT  (SEQ / 64)
#define BUFB (128 * KLD * 2)      // bytes per KV buffer

__global__ void __launch_bounds__(128, 3)
attn_tc(const __half* __restrict__ Qp, const __half* __restrict__ Kp,
        const __half* __restrict__ Vt, const int* __restrict__ mask,
        float* __restrict__ Ctx)
{
    __shared__ __half KV[2][128 * KLD];

    const int tid = threadIdx.x;
    const int lane = tid & 31, wid = tid >> 5;
    const int g = lane >> 2, tig = lane & 3;
    const int b = blockIdx.y / HEADS, h = blockIdx.y % HEADS;
    const int q0 = blockIdx.x * 128;
    const int qb = wid * 32;

    const __half* kg = Kp + ((size_t)b * SEQ) * DMODEL + h * DK;
    const __half* vg = Vt + ((size_t)(b * DMODEL + h * DK)) * SEQ;
    const int* mg = mask + b * SEQ;

    // ---- stage Q (fp16, pre-scaled) through KV[0], lift A-frags ----
    {
        const __half* qg = Qp + ((size_t)(b * SEQ + q0)) * DMODEL + h * DK;
        #pragma unroll
        for (int i = 0; i < 8; i++) {
            const int L = tid + i * 128;
            const int r = L >> 3, c8 = (L & 7) * 8;
            *(uint4*)(KV[0] + r * KLD + c8) =
                *(const uint4*)(qg + (size_t)r * DMODEL + c8);
        }
    }
    __syncthreads();

    uint32_t qf[4][2][4];
    #pragma unroll
    for (int c = 0; c < 4; c++) {
        const int kk = 16 * c + 2 * tig;
        #pragma unroll
        for (int i = 0; i < 2; i++) {
            const int rb = qb + 16 * i;
            qf[c][i][0] = *(const uint32_t*)&KV[0][(rb + g) * KLD + kk];
            qf[c][i][1] = *(const uint32_t*)&KV[0][(rb + 8 + g) * KLD + kk];
            qf[c][i][2] = *(const uint32_t*)&KV[0][(rb + g) * KLD + kk + 8];
            qf[c][i][3] = *(const uint32_t*)&KV[0][(rb + 8 + g) * KLD + kk + 8];
        }
    }
    __syncthreads();

    // ---- hoisted prefetch addressing (loop-invariant) ----
    const int pr = tid >> 3;              // 0..15
    const int pc = (tid & 7) * 8;         // 0..56
    const __half* ksrc = kg + (size_t)pr * DMODEL + pc;
    const __half* vsrc = vg + (size_t)pr * SEQ + pc;
    const uint32_t dk0 =
        (uint32_t)__cvta_generic_to_shared(&KV[0][pr * KLD + pc]);

    float o[2][8][4] = {};
    float l00 = 0.f, l01 = 0.f, l10 = 0.f, l11 = 0.f;

    // prefetch tile 0 into buffer 0 (immediate offsets only)
    {
        const uint32_t dV = dk0 + 64 * KLD * 2;
        #pragma unroll
        for (int i = 0; i < 4; i++) {
            cpa16r(dk0 + i * (16 * KLD * 2), ksrc + (size_t)i * 16 * DMODEL);
            cpa16r(dV + i * (16 * KLD * 2), vsrc + (size_t)i * 16 * SEQ);
        }
        CPA_COMMIT();
        ksrc += (size_t)64 * DMODEL;
        vsrc += 64;
    }

    for (int kt = 0; kt < NT; kt++) {
        const int cur = kt & 1;
        const __half* Ks = KV[cur];
        const __half* Vs = KV[cur] + 64 * KLD;

        // mask word for the all-ones test (L2-hot; issued early)
        const int mv = __ldg(mg + kt * 64 + (tid & 63));

        if (kt + 1 < NT) {
            const uint32_t dK = dk0 + (cur ^ 1) * BUFB;
            const uint32_t dV = dK + 64 * KLD * 2;
            #pragma unroll
            for (int i = 0; i < 4; i++) {
                cpa16r(dK + i * (16 * KLD * 2), ksrc + (size_t)i * 16 * DMODEL);
                cpa16r(dV + i * (16 * KLD * 2), vsrc + (size_t)i * 16 * SEQ);
            }
            CPA_COMMIT();
            ksrc += (size_t)64 * DMODEL;
            vsrc += 64;
            CPA_WAIT1();            // tile kt complete, kt+1 in flight
        } else {
            CPA_WAIT0();
        }
        // barrier (makes staged tile visible) + all-ones mask reduction
        const int allone = __syncthreads_and(mv != 0);

        // ---- S = Q K^T ----
        float s[2][8][4] = {};
        #pragma unroll
        for (int c = 0; c < 4; c++) {
            const int kk = 16 * c + 2 * tig;
            #pragma unroll
            for (int j = 0; j < 8; j++) {
                const int rn = (j * 8 + g) * KLD + kk;
                uint32_t b0 = *(const uint32_t*)&Ks[rn];
                uint32_t b1 = *(const uint32_t*)&Ks[rn + 8];
                mma16(s[0][j], qf[c][0], b0, b1);
                mma16(s[1][j], qf[c][1], b0, b1);
            }
        }

        // ---- softmax; repack P in registers as O-mma A-fragments ----
        uint32_t pa[2][8][2];
        if (allone) {
            #pragma unroll
            for (int j = 0; j < 8; j++) {
                float p0 = __expf(s[0][j][0]);
                float p1 = __expf(s[0][j][1]);
                float p2 = __expf(s[0][j][2]);
                float p3 = __expf(s[0][j][3]);
                l00 += p0 + p1; l01 += p2 + p3;
                pa[0][j][0] = packh2(p0, p1);
                pa[0][j][1] = packh2(p2, p3);
                float q0f = __expf(s[1][j][0]);
                float q1f = __expf(s[1][j][1]);
                float q2f = __expf(s[1][j][2]);
                float q3f = __expf(s[1][j][3]);
                l10 += q0f + q1f; l11 += q2f + q3f;
                pa[1][j][0] = packh2(q0f, q1f);
                pa[1][j][1] = packh2(q2f, q3f);
            }
        } else {
            #pragma unroll
            for (int j = 0; j < 8; j++) {
                int2 mi = __ldg((const int2*)(mg + kt * 64 + j * 8 + 2 * tig));
                float p0 = mi.x ? __expf(s[0][j][0]) : 0.f;
                float p1 = mi.y ? __expf(s[0][j][1]) : 0.f;
                float p2 = mi.x ? __expf(s[0][j][2]) : 0.f;
                float p3 = mi.y ? __expf(s[0][j][3]) : 0.f;
                l00 += p0 + p1; l01 += p2 + p3;
                pa[0][j][0] = packh2(p0, p1);
                pa[0][j][1] = packh2(p2, p3);
                float q0f = mi.x ? __expf(s[1][j][0]) : 0.f;
                float q1f = mi.y ? __expf(s[1][j][1]) : 0.f;
                float q2f = mi.x ? __expf(s[1][j][2]) : 0.f;
                float q3f = mi.y ? __expf(s[1][j][3]) : 0.f;
                l10 += q0f + q1f; l11 += q2f + q3f;
                pa[1][j][0] = packh2(q0f, q1f);
                pa[1][j][1] = packh2(q2f, q3f);
            }
        }

        // ---- O += P V^T ----
        #pragma unroll
        for (int m = 0; m < 4; m++) {
            uint32_t av0[4] = { pa[0][2 * m][0], pa[0][2 * m][1],
                                pa[0][2 * m + 1][0], pa[0][2 * m + 1][1] };
            uint32_t av1[4] = { pa[1][2 * m][0], pa[1][2 * m][1],
                                pa[1][2 * m + 1][0], pa[1][2 * m + 1][1] };
            const int kk = 16 * m + 2 * tig;
            #pragma unroll
            for (int j = 0; j < 8; j++) {
                const int rn = (j * 8 + g) * KLD + kk;
                uint32_t b0 = *(const uint32_t*)&Vs[rn];
                uint32_t b1 = *(const uint32_t*)&Vs[rn + 8];
                mma16(o[0][j], av0, b0, b1);
                mma16(o[1][j], av1, b0, b1);
            }
        }
        __syncthreads();            // protect buffer cur^1 before next prefetch
    }

    // ---- finalize ----
    l00 += __shfl_xor_sync(0xffffffffu, l00, 1);
    l00 += __shfl_xor_sync(0xffffffffu, l00, 2);
    l01 += __shfl_xor_sync(0xffffffffu, l01, 1);
    l01 += __shfl_xor_sync(0xffffffffu, l01, 2);
    l10 += __shfl_xor_sync(0xffffffffu, l10, 1);
    l10 += __shfl_xor_sync(0xffffffffu, l10, 2);
    l11 += __shfl_xor_sync(0xffffffffu, l11, 1);
    l11 += __shfl_xor_sync(0xffffffffu, l11, 2);
    const float inv[2][2] = { {1.f / l00, 1.f / l01}, {1.f / l10, 1.f / l11} };

    #pragma unroll
    for (int i = 0; i < 2; i++) {
        float* cg = Ctx + ((size_t)(b * SEQ + q0 + qb + 16 * i)) * DMODEL + h * DK;
        #pragma unroll
        for (int j = 0; j < 8; j++) {
            const int col = j * 8 + 2 * tig;
            *(float2*)(cg + (size_t)g * DMODEL + col) =
                make_float2(o[i][j][0] * inv[i][0], o[i][j][1] * inv[i][0]);
            *(float2*)(cg + (size_t)(8 + g) * DMODEL + col) =
                make_float2(o[i][j][2] * inv[i][1], o[i][j][3] * inv[i][1]);
        }
    }
}

// ---------------------------------------------------------------------------
// Launcher.  Inputs: q, k, v, Wq, bq, Wk, bk, Wv, bv, Wo, bo, mask
// ---------------------------------------------------------------------------
extern "C" void kernel_launch(void* const* d_in, const int* in_sizes, int n_in,
                              void* d_out, int out_size)
{
    const float* q    = (const float*)d_in[0];
    const float* k    = (const float*)d_in[1];
    const float* v    = (const float*)d_in[2];
    const float* Wq   = (const float*)d_in[3];
    const float* bq   = (const float*)d_in[4];
    const float* Wk   = (const float*)d_in[5];
    const float* bk   = (const float*)d_in[6];
    const float* Wv   = (const float*)d_in[7];
    const float* bv   = (const float*)d_in[8];
    const float* Wo   = (const float*)d_in[9];
    const float* bo   = (const float*)d_in[10];
    const int*   mask = (const int*)d_in[11];
    float* out = (float*)d_out;

    __half *Qp, *Kp, *Vt;
    float *Ctx;
    cudaGetSymbolAddress((void**)&Qp,  g_Qp);
    cudaGetSymbolAddress((void**)&Kp,  g_Kp);
    cudaGetSymbolAddress((void**)&Vt,  g_Vt);
    cudaGetSymbolAddress((void**)&Ctx, g_Ctx);

    dim3 ggrid(DMODEL / GBN, MROWS / GBM);   // (6, 64)
    dim3 gblk(256);

    gemm_tc<__half, 0><<<ggrid, gblk>>>(q, Wq, bq, Qp, MROWS, DMODEL, DMODEL, 0.125f);
    gemm_tc<__half, 0><<<ggrid, gblk>>>(k, Wk, bk, Kp, MROWS, DMODEL, DMODEL, 1.0f);
    gemm_tc<__half, 1><<<ggrid, gblk>>>(v, Wv, bv, Vt, MROWS, DMODEL, DMODEL, 1.0f);

    dim3 agrid(SEQ / 128, BS * HEADS);       // (32, 24)
    attn_tc<<<agrid, 128>>>(Qp, Kp, Vt, mask, Ctx);

    gemm_tc<float, 0><<<ggrid, gblk>>>(Ctx, Wo, bo, out, MROWS, DMODEL, DMODEL, 1.0f);
}

// round 10
// speedup vs baseline: 1.1034x; 1.0039x over previous
#include <cuda_runtime.h>
#include <cuda_fp16.h>
#include <cstdint>

// ---------------------------------------------------------------------------
// Problem constants
// ---------------------------------------------------------------------------
#define BS      2
#define SEQ     4096
#define DMODEL  768
#define HEADS   12
#define DK      64
#define MROWS   (BS * SEQ)          // 8192

// ---------------------------------------------------------------------------
// Scratch (device globals; no cudaMalloc allowed)
// ---------------------------------------------------------------------------
__device__ __half g_Qp[MROWS * DMODEL];              // prescaled by 1/8
__device__ __half g_Kp[MROWS * DMODEL];
__device__ __half g_Vt[(size_t)BS * DMODEL * SEQ];   // [b][dmodel][seq]
__device__ float  g_Ctx[MROWS * DMODEL];

// ---------------------------------------------------------------------------
// Helpers
// ---------------------------------------------------------------------------
__device__ __forceinline__ void mma16(float* d, const uint32_t* a,
                                      uint32_t b0, uint32_t b1) {
    asm volatile(
        "mma.sync.aligned.m16n8k16.row.col.f32.f16.f16.f32 "
        "{%0,%1,%2,%3}, {%4,%5,%6,%7}, {%8,%9}, {%0,%1,%2,%3};"
        : "+f"(d[0]), "+f"(d[1]), "+f"(d[2]), "+f"(d[3])
        : "r"(a[0]), "r"(a[1]), "r"(a[2]), "r"(a[3]), "r"(b0), "r"(b1));
}

__device__ __forceinline__ uint32_t packh2(float a, float b) {
    __half2 h = __floats2half2_rn(a, b);
    return *(uint32_t*)&h;
}

__device__ __forceinline__ void st_h4(__half* p, float4 v) {
    uint2 u;
    u.x = packh2(v.x, v.y);
    u.y = packh2(v.z, v.w);
    *(uint2*)p = u;
}

// cp.async with precomputed shared-address (uint32) destination
__device__ __forceinline__ void cpa16r(uint32_t dst, const void* src) {
    asm volatile("cp.async.cg.shared.global [%0], [%1], 16;"
                 :: "r"(dst), "l"(src));
}
#define CPA_COMMIT() asm volatile("cp.async.commit_group;" ::: "memory")
#define CPA_WAIT1()  asm volatile("cp.async.wait_group 1;" ::: "memory")
#define CPA_WAIT0()  asm volatile("cp.async.wait_group 0;" ::: "memory")

// ---------------------------------------------------------------------------
// GEMM: C[M,N] = (A[M,K] @ B[N,K]^T + bias[N]) * scale  (round-7/8 proven)
// ---------------------------------------------------------------------------
#define GBM 128
#define GBN 128
#define GBK 32
#define GLDH 40

template <typename OutT, int TRANS>
__global__ __launch_bounds__(256, 2) void gemm_tc(
    const float* __restrict__ A, const float* __restrict__ B,
    const float* __restrict__ bias, OutT* __restrict__ C,
    int M, int N, int K, float scale)
{
    __shared__ __half As[GBM * GLDH];
    __shared__ __half Bs[GBN * GLDH];

    const int tid = threadIdx.x;
    const int lane = tid & 31, wid = tid >> 5;
    const int g = lane >> 2, tig = lane & 3;
    const int wm = (wid & 3) * 32, wn = (wid >> 2) * 64;
    const int row0 = blockIdx.y * GBM, col0 = blockIdx.x * GBN;

    const int r = tid >> 3;
    const int c4 = (tid & 7) * 4;
    const float* Aptr = A + (size_t)(row0 + r) * K + c4;
    const float* Bptr = B + (size_t)(col0 + r) * K + c4;

    float4 pa[4], pb[4];
    #pragma unroll
    for (int m = 0; m < 4; m++) {
        pa[m] = *(const float4*)(Aptr + (size_t)(32 * m) * K);
        pb[m] = *(const float4*)(Bptr + (size_t)(32 * m) * K);
    }

    float acc[2][8][4] = {};

    int k0 = 0;
    while (true) {
        __syncthreads();
        #pragma unroll
        for (int m = 0; m < 4; m++) {
            st_h4(As + (r + 32 * m) * GLDH + c4, pa[m]);
            st_h4(Bs + (r + 32 * m) * GLDH + c4, pb[m]);
        }
        __syncthreads();

        k0 += GBK;
        const bool more = (k0 < K);
        if (more) {
            #pragma unroll
            for (int m = 0; m < 4; m++) {
                pa[m] = *(const float4*)(Aptr + (size_t)(32 * m) * K + k0);
                pb[m] = *(const float4*)(Bptr + (size_t)(32 * m) * K + k0);
            }
        }

        #pragma unroll
        for (int c = 0; c < 2; c++) {
            const int kk = 16 * c + 2 * tig;
            uint32_t a[2][4];
            #pragma unroll
            for (int i = 0; i < 2; i++) {
                const int rb = wm + 16 * i;
                a[i][0] = *(const uint32_t*)&As[(rb + g) * GLDH + kk];
                a[i][1] = *(const uint32_t*)&As[(rb + 8 + g) * GLDH + kk];
                a[i][2] = *(const uint32_t*)&As[(rb + g) * GLDH + kk + 8];
                a[i][3] = *(const uint32_t*)&As[(rb + 8 + g) * GLDH + kk + 8];
            }
            #pragma unroll
            for (int j = 0; j < 8; j++) {
                const int cn = wn + j * 8 + g;
                uint32_t b0 = *(const uint32_t*)&Bs[cn * GLDH + kk];
                uint32_t b1 = *(const uint32_t*)&Bs[cn * GLDH + kk + 8];
                mma16(acc[0][j], a[0], b0, b1);
                mma16(acc[1][j], a[1], b0, b1);
            }
        }
        if (!more) break;
    }

    #pragma unroll
    for (int i = 0; i < 2; i++) {
        const int rA = row0 + wm + i * 16 + g;
        const int rB = rA + 8;
        #pragma unroll
        for (int j = 0; j < 8; j++) {
            const int col = col0 + wn + j * 8 + 2 * tig;
            const float bx = __ldg(bias + col), by = __ldg(bias + col + 1);
            const float v0 = (acc[i][j][0] + bx) * scale;
            const float v1 = (acc[i][j][1] + by) * scale;
            const float v2 = (acc[i][j][2] + bx) * scale;
            const float v3 = (acc[i][j][3] + by) * scale;
            if (TRANS == 0) {
                if (sizeof(OutT) == 2) {
                    __half2* pA = (__half2*)((__half*)C + (size_t)rA * N + col);
                    __half2* pB = (__half2*)((__half*)C + (size_t)rB * N + col);
                    *pA = __floats2half2_rn(v0, v1);
                    *pB = __floats2half2_rn(v2, v3);
                } else {
                    *(float2*)((float*)C + (size_t)rA * N + col) = make_float2(v0, v1);
                    *(float2*)((float*)C + (size_t)rB * N + col) = make_float2(v2, v3);
                }
            } else {
                const int bA = rA >> 12, sA = rA & (SEQ - 1);
                const int bB = rB >> 12, sB = rB & (SEQ - 1);
                C[((size_t)bA * DMODEL + col)     * SEQ + sA] = (OutT)v0;
                C[((size_t)bA * DMODEL + col + 1) * SEQ + sA] = (OutT)v1;
                C[((size_t)bB * DMODEL + col)     * SEQ + sB] = (OutT)v2;
                C[((size_t)bB * DMODEL + col + 1) * SEQ + sB] = (OutT)v3;
            }
        }
    }
}

// ---------------------------------------------------------------------------
// Attention: fp16 mma, 32-q warp tiles, cp.async double-buffer with hoisted
// addresses, mask handled by bar.red.and fast path.
// CTA = (b, h, 128-query tile), 128 threads = 4 warps x 32 q-rows.
// ---------------------------------------------------------------------------
#define KLD 72
#define NT  (SEQ / 64)
#define BUFB (128 * KLD * 2)      // bytes per KV buffer

__global__ void __launch_bounds__(128, 3)
attn_tc(const __half* __restrict__ Qp, const __half* __restrict__ Kp,
        const __half* __restrict__ Vt, const int* __restrict__ mask,
        float* __restrict__ Ctx)
{
    __shared__ __half KV[2][128 * KLD];

    const int tid = threadIdx.x;
    const int lane = tid & 31, wid = tid >> 5;
    const int g = lane >> 2, tig = lane & 3;
    const int b = blockIdx.y / HEADS, h = blockIdx.y % HEADS;
    const int q0 = blockIdx.x * 128;
    const int qb = wid * 32;

    const __half* kg = Kp + ((size_t)b * SEQ) * DMODEL + h * DK;
    const __half* vg = Vt + ((size_t)(b * DMODEL + h * DK)) * SEQ;
    const int* mg = mask + b * SEQ;

    // ---- stage Q (fp16, pre-scaled) through KV[0], lift A-frags ----
    {
        const __half* qg = Qp + ((size_t)(b * SEQ + q0)) * DMODEL + h * DK;
        #pragma unroll
        for (int i = 0; i < 8; i++) {
            const int L = tid + i * 128;
            const int r = L >> 3, c8 = (L & 7) * 8;
            *(uint4*)(KV[0] + r * KLD + c8) =
                *(const uint4*)(qg + (size_t)r * DMODEL + c8);
        }
    }
    __syncthreads();

    uint32_t qf[4][2][4];
    #pragma unroll
    for (int c = 0; c < 4; c++) {
        const int kk = 16 * c + 2 * tig;
        #pragma unroll
        for (int i = 0; i < 2; i++) {
            const int rb = qb + 16 * i;
            qf[c][i][0] = *(const uint32_t*)&KV[0][(rb + g) * KLD + kk];
            qf[c][i][1] = *(const uint32_t*)&KV[0][(rb + 8 + g) * KLD + kk];
            qf[c][i][2] = *(const uint32_t*)&KV[0][(rb + g) * KLD + kk + 8];
            qf[c][i][3] = *(const uint32_t*)&KV[0][(rb + 8 + g) * KLD + kk + 8];
        }
    }
    __syncthreads();

    // ---- hoisted prefetch addressing (loop-invariant) ----
    const int pr = tid >> 3;              // 0..15
    const int pc = (tid & 7) * 8;         // 0..56
    const __half* ksrc = kg + (size_t)pr * DMODEL + pc;
    const __half* vsrc = vg + (size_t)pr * SEQ + pc;
    const uint32_t dk0 =
        (uint32_t)__cvta_generic_to_shared(&KV[0][pr * KLD + pc]);

    float o[2][8][4] = {};
    float l00 = 0.f, l01 = 0.f, l10 = 0.f, l11 = 0.f;

    // prefetch tile 0 into buffer 0 (immediate offsets only)
    {
        const uint32_t dV = dk0 + 64 * KLD * 2;
        #pragma unroll
        for (int i = 0; i < 4; i++) {
            cpa16r(dk0 + i * (16 * KLD * 2), ksrc + (size_t)i * 16 * DMODEL);
            cpa16r(dV + i * (16 * KLD * 2), vsrc + (size_t)i * 16 * SEQ);
        }
        CPA_COMMIT();
        ksrc += (size_t)64 * DMODEL;
        vsrc += 64;
    }

    for (int kt = 0; kt < NT; kt++) {
        const int cur = kt & 1;
        const __half* Ks = KV[cur];
        const __half* Vs = KV[cur] + 64 * KLD;

        // mask word for the all-ones test (L2-hot; issued early)
        const int mv = __ldg(mg + kt * 64 + (tid & 63));

        if (kt + 1 < NT) {
            const uint32_t dK = dk0 + (cur ^ 1) * BUFB;
            const uint32_t dV = dK + 64 * KLD * 2;
            #pragma unroll
            for (int i = 0; i < 4; i++) {
                cpa16r(dK + i * (16 * KLD * 2), ksrc + (size_t)i * 16 * DMODEL);
                cpa16r(dV + i * (16 * KLD * 2), vsrc + (size_t)i * 16 * SEQ);
            }
            CPA_COMMIT();
            ksrc += (size_t)64 * DMODEL;
            vsrc += 64;
            CPA_WAIT1();            // tile kt complete, kt+1 in flight
        } else {
            CPA_WAIT0();
        }
        // barrier (makes staged tile visible) + all-ones mask reduction
        const int allone = __syncthreads_and(mv != 0);

        // ---- S = Q K^T ----
        float s[2][8][4] = {};
        #pragma unroll
        for (int c = 0; c < 4; c++) {
            const int kk = 16 * c + 2 * tig;
            #pragma unroll
            for (int j = 0; j < 8; j++) {
                const int rn = (j * 8 + g) * KLD + kk;
                uint32_t b0 = *(const uint32_t*)&Ks[rn];
                uint32_t b1 = *(const uint32_t*)&Ks[rn + 8];
                mma16(s[0][j], qf[c][0], b0, b1);
                mma16(s[1][j], qf[c][1], b0, b1);
            }
        }

        // ---- softmax; repack P in registers as O-mma A-fragments ----
        uint32_t pa[2][8][2];
        if (allone) {
            #pragma unroll
            for (int j = 0; j < 8; j++) {
                float p0 = __expf(s[0][j][0]);
                float p1 = __expf(s[0][j][1]);
                float p2 = __expf(s[0][j][2]);
                float p3 = __expf(s[0][j][3]);
                l00 += p0 + p1; l01 += p2 + p3;
                pa[0][j][0] = packh2(p0, p1);
                pa[0][j][1] = packh2(p2, p3);
                float q0f = __expf(s[1][j][0]);
                float q1f = __expf(s[1][j][1]);
                float q2f = __expf(s[1][j][2]);
                float q3f = __expf(s[1][j][3]);
                l10 += q0f + q1f; l11 += q2f + q3f;
                pa[1][j][0] = packh2(q0f, q1f);
                pa[1][j][1] = packh2(q2f, q3f);
            }
        } else {
            #pragma unroll
            for (int j = 0; j < 8; j++) {
                int2 mi = __ldg((const int2*)(mg + kt * 64 + j * 8 + 2 * tig));
                float p0 = mi.x ? __expf(s[0][j][0]) : 0.f;
                float p1 = mi.y ? __expf(s[0][j][1]) : 0.f;
                float p2 = mi.x ? __expf(s[0][j][2]) : 0.f;
                float p3 = mi.y ? __expf(s[0][j][3]) : 0.f;
                l00 += p0 + p1; l01 += p2 + p3;
                pa[0][j][0] = packh2(p0, p1);
                pa[0][j][1] = packh2(p2, p3);
                float q0f = mi.x ? __expf(s[1][j][0]) : 0.f;
                float q1f = mi.y ? __expf(s[1][j][1]) : 0.f;
                float q2f = mi.x ? __expf(s[1][j][2]) : 0.f;
                float q3f = mi.y ? __expf(s[1][j][3]) : 0.f;
                l10 += q0f + q1f; l11 += q2f + q3f;
                pa[1][j][0] = packh2(q0f, q1f);
                pa[1][j][1] = packh2(q2f, q3f);
            }
        }

        // ---- O += P V^T ----
        #pragma unroll
        for (int m = 0; m < 4; m++) {
            uint32_t av0[4] = { pa[0][2 * m][0], pa[0][2 * m][1],
                                pa[0][2 * m + 1][0], pa[0][2 * m + 1][1] };
            uint32_t av1[4] = { pa[1][2 * m][0], pa[1][2 * m][1],
                                pa[1][2 * m + 1][0], pa[1][2 * m + 1][1] };
            const int kk = 16 * m + 2 * tig;
            #pragma unroll
            for (int j = 0; j < 8; j++) {
                const int rn = (j * 8 + g) * KLD + kk;
                uint32_t b0 = *(const uint32_t*)&Vs[rn];
                uint32_t b1 = *(const uint32_t*)&Vs[rn + 8];
                mma16(o[0][j], av0, b0, b1);
                mma16(o[1][j], av1, b0, b1);
            }
        }
        __syncthreads();            // protect buffer cur^1 before next prefetch
    }

    // ---- finalize ----
    l00 += __shfl_xor_sync(0xffffffffu, l00, 1);
    l00 += __shfl_xor_sync(0xffffffffu, l00, 2);
    l01 += __shfl_xor_sync(0xffffffffu, l01, 1);
    l01 += __shfl_xor_sync(0xffffffffu, l01, 2);
    l10 += __shfl_xor_sync(0xffffffffu, l10, 1);
    l10 += __shfl_xor_sync(0xffffffffu, l10, 2);
    l11 += __shfl_xor_sync(0xffffffffu, l11, 1);
    l11 += __shfl_xor_sync(0xffffffffu, l11, 2);
    const float inv[2][2] = { {1.f / l00, 1.f / l01}, {1.f / l10, 1.f / l11} };

    #pragma unroll
    for (int i = 0; i < 2; i++) {
        float* cg = Ctx + ((size_t)(b * SEQ + q0 + qb + 16 * i)) * DMODEL + h * DK;
        #pragma unroll
        for (int j = 0; j < 8; j++) {
            const int col = j * 8 + 2 * tig;
            *(float2*)(cg + (size_t)g * DMODEL + col) =
                make_float2(o[i][j][0] * inv[i][0], o[i][j][1] * inv[i][0]);
            *(float2*)(cg + (size_t)(8 + g) * DMODEL + col) =
                make_float2(o[i][j][2] * inv[i][1], o[i][j][3] * inv[i][1]);
        }
    }
}

// ---------------------------------------------------------------------------
// Launcher.  Inputs: q, k, v, Wq, bq, Wk, bk, Wv, bv, Wo, bo, mask
// ---------------------------------------------------------------------------
extern "C" void kernel_launch(void* const* d_in, const int* in_sizes, int n_in,
                              void* d_out, int out_size)
{
    const float* q    = (const float*)d_in[0];
    const float* k    = (const float*)d_in[1];
    const float* v    = (const float*)d_in[2];
    const float* Wq   = (const float*)d_in[3];
    const float* bq   = (const float*)d_in[4];
    const float* Wk   = (const float*)d_in[5];
    const float* bk   = (const float*)d_in[6];
    const float* Wv   = (const float*)d_in[7];
    const float* bv   = (const float*)d_in[8];
    const float* Wo   = (const float*)d_in[9];
    const float* bo   = (const float*)d_in[10];
    const int*   mask = (const int*)d_in[11];
    float* out = (float*)d_out;

    __half *Qp, *Kp, *Vt;
    float *Ctx;
    cudaGetSymbolAddress((void**)&Qp,  g_Qp);
    cudaGetSymbolAddress((void**)&Kp,  g_Kp);
    cudaGetSymbolAddress((void**)&Vt,  g_Vt);
    cudaGetSymbolAddress((void**)&Ctx, g_Ctx);

    dim3 ggrid(DMODEL / GBN, MROWS / GBM);   // (6, 64)
    dim3 gblk(256);

    gemm_tc<__half, 0><<<ggrid, gblk>>>(q, Wq, bq, Qp, MROWS, DMODEL, DMODEL, 0.125f);
    gemm_tc<__half, 0><<<ggrid, gblk>>>(k, Wk, bk, Kp, MROWS, DMODEL, DMODEL, 1.0f);
    gemm_tc<__half, 1><<<ggrid, gblk>>>(v, Wv, bv, Vt, MROWS, DMODEL, DMODEL, 1.0f);

    dim3 agrid(SEQ / 128, BS * HEADS);       // (32, 24)
    attn_tc<<<agrid, 128>>>(Qp, Kp, Vt, mask, Ctx);

    gemm_tc<float, 0><<<ggrid, gblk>>>(Ctx, Wo, bo, out, MROWS, DMODEL, DMODEL, 1.0f);
}

// round 11
// speedup vs baseline: 1.1794x; 1.0689x over previous
#include <cuda_runtime.h>
#include <cuda_fp16.h>
#include <cstdint>

// ---------------------------------------------------------------------------
// Problem constants
// ---------------------------------------------------------------------------
#define BS      2
#define SEQ     4096
#define DMODEL  768
#define HEADS   12
#define DK      64
#define MROWS   (BS * SEQ)          // 8192

// ---------------------------------------------------------------------------
// Scratch (device globals; no cudaMalloc allowed)
// ---------------------------------------------------------------------------
__device__ __half g_Qp[MROWS * DMODEL];              // prescaled by log2e/8
__device__ __half g_Kp[MROWS * DMODEL];
__device__ __half g_Vt[(size_t)BS * DMODEL * SEQ];   // [b][dmodel][seq]
__device__ float  g_Ctx[MROWS * DMODEL];

// ---------------------------------------------------------------------------
// Helpers
// ---------------------------------------------------------------------------
__device__ __forceinline__ void mma16(float* d, const uint32_t* a,
                                      uint32_t b0, uint32_t b1) {
    asm volatile(
        "mma.sync.aligned.m16n8k16.row.col.f32.f16.f16.f32 "
        "{%0,%1,%2,%3}, {%4,%5,%6,%7}, {%8,%9}, {%0,%1,%2,%3};"
        : "+f"(d[0]), "+f"(d[1]), "+f"(d[2]), "+f"(d[3])
        : "r"(a[0]), "r"(a[1]), "r"(a[2]), "r"(a[3]), "r"(b0), "r"(b1));
}

__device__ __forceinline__ uint32_t packh2(float a, float b) {
    __half2 h = __floats2half2_rn(a, b);
    return *(uint32_t*)&h;
}

__device__ __forceinline__ uint32_t ex2h2(uint32_t x) {
    uint32_t r;
    asm("ex2.approx.f16x2 %0, %1;" : "=r"(r) : "r"(x));
    return r;
}

__device__ __forceinline__ void st_h4(__half* p, float4 v) {
    uint2 u;
    u.x = packh2(v.x, v.y);
    u.y = packh2(v.z, v.w);
    *(uint2*)p = u;
}

// cp.async with precomputed shared-address (uint32) destination
__device__ __forceinline__ void cpa16r(uint32_t dst, const void* src) {
    asm volatile("cp.async.cg.shared.global [%0], [%1], 16;"
                 :: "r"(dst), "l"(src));
}
#define CPA_COMMIT() asm volatile("cp.async.commit_group;" ::: "memory")
#define CPA_WAIT1()  asm volatile("cp.async.wait_group 1;" ::: "memory")
#define CPA_WAIT0()  asm volatile("cp.async.wait_group 0;" ::: "memory")

// ---------------------------------------------------------------------------
// GEMM: C[M,N] = (A[M,K] @ B[N,K]^T + bias[N]) * scale  (round-7/8 proven)
// ---------------------------------------------------------------------------
#define GBM 128
#define GBN 128
#define GBK 32
#define GLDH 40

template <typename OutT, int TRANS>
__global__ __launch_bounds__(256, 2) void gemm_tc(
    const float* __restrict__ A, const float* __restrict__ B,
    const float* __restrict__ bias, OutT* __restrict__ C,
    int M, int N, int K, float scale)
{
    __shared__ __half As[GBM * GLDH];
    __shared__ __half Bs[GBN * GLDH];

    const int tid = threadIdx.x;
    const int lane = tid & 31, wid = tid >> 5;
    const int g = lane >> 2, tig = lane & 3;
    const int wm = (wid & 3) * 32, wn = (wid >> 2) * 64;
    const int row0 = blockIdx.y * GBM, col0 = blockIdx.x * GBN;

    const int r = tid >> 3;
    const int c4 = (tid & 7) * 4;
    const float* Aptr = A + (size_t)(row0 + r) * K + c4;
    const float* Bptr = B + (size_t)(col0 + r) * K + c4;

    float4 pa[4], pb[4];
    #pragma unroll
    for (int m = 0; m < 4; m++) {
        pa[m] = *(const float4*)(Aptr + (size_t)(32 * m) * K);
        pb[m] = *(const float4*)(Bptr + (size_t)(32 * m) * K);
    }

    float acc[2][8][4] = {};

    int k0 = 0;
    while (true) {
        __syncthreads();
        #pragma unroll
        for (int m = 0; m < 4; m++) {
            st_h4(As + (r + 32 * m) * GLDH + c4, pa[m]);
            st_h4(Bs + (r + 32 * m) * GLDH + c4, pb[m]);
        }
        __syncthreads();

        k0 += GBK;
        const bool more = (k0 < K);
        if (more) {
            #pragma unroll
            for (int m = 0; m < 4; m++) {
                pa[m] = *(const float4*)(Aptr + (size_t)(32 * m) * K + k0);
                pb[m] = *(const float4*)(Bptr + (size_t)(32 * m) * K + k0);
            }
        }

        #pragma unroll
        for (int c = 0; c < 2; c++) {
            const int kk = 16 * c + 2 * tig;
            uint32_t a[2][4];
            #pragma unroll
            for (int i = 0; i < 2; i++) {
                const int rb = wm + 16 * i;
                a[i][0] = *(const uint32_t*)&As[(rb + g) * GLDH + kk];
                a[i][1] = *(const uint32_t*)&As[(rb + 8 + g) * GLDH + kk];
                a[i][2] = *(const uint32_t*)&As[(rb + g) * GLDH + kk + 8];
                a[i][3] = *(const uint32_t*)&As[(rb + 8 + g) * GLDH + kk + 8];
            }
            #pragma unroll
            for (int j = 0; j < 8; j++) {
                const int cn = wn + j * 8 + g;
                uint32_t b0 = *(const uint32_t*)&Bs[cn * GLDH + kk];
                uint32_t b1 = *(const uint32_t*)&Bs[cn * GLDH + kk + 8];
                mma16(acc[0][j], a[0], b0, b1);
                mma16(acc[1][j], a[1], b0, b1);
            }
        }
        if (!more) break;
    }

    #pragma unroll
    for (int i = 0; i < 2; i++) {
        const int rA = row0 + wm + i * 16 + g;
        const int rB = rA + 8;
        #pragma unroll
        for (int j = 0; j < 8; j++) {
            const int col = col0 + wn + j * 8 + 2 * tig;
            const float bx = __ldg(bias + col), by = __ldg(bias + col + 1);
            const float v0 = (acc[i][j][0] + bx) * scale;
            const float v1 = (acc[i][j][1] + by) * scale;
            const float v2 = (acc[i][j][2] + bx) * scale;
            const float v3 = (acc[i][j][3] + by) * scale;
            if (TRANS == 0) {
                if (sizeof(OutT) == 2) {
                    __half2* pA = (__half2*)((__half*)C + (size_t)rA * N + col);
                    __half2* pB = (__half2*)((__half*)C + (size_t)rB * N + col);
                    *pA = __floats2half2_rn(v0, v1);
                    *pB = __floats2half2_rn(v2, v3);
                } else {
                    *(float2*)((float*)C + (size_t)rA * N + col) = make_float2(v0, v1);
                    *(float2*)((float*)C + (size_t)rB * N + col) = make_float2(v2, v3);
                }
            } else {
                const int bA = rA >> 12, sA = rA & (SEQ - 1);
                const int bB = rB >> 12, sB = rB & (SEQ - 1);
                C[((size_t)bA * DMODEL + col)     * SEQ + sA] = (OutT)v0;
                C[((size_t)bA * DMODEL + col + 1) * SEQ + sA] = (OutT)v1;
                C[((size_t)bB * DMODEL + col)     * SEQ + sB] = (OutT)v2;
                C[((size_t)bB * DMODEL + col + 1) * SEQ + sB] = (OutT)v3;
            }
        }
    }
}

// ---------------------------------------------------------------------------
// Attention: fp16 mma, 32-q warp tiles, cp.async double-buffer.
// Softmax: Q prescaled by log2e/8 -> scores in exp2 domain; p = ex2.f16x2
// (cvt output IS the P fragment); row sums via ones-MMA into fp32 C frags.
// CTA = (b, h, 128-query tile), 128 threads = 4 warps x 32 q-rows.
// ---------------------------------------------------------------------------
#define KLD 72
#define NT  (SEQ / 64)
#define BUFB (128 * KLD * 2)      // bytes per KV buffer

__global__ void __launch_bounds__(128, 3)
attn_tc(const __half* __restrict__ Qp, const __half* __restrict__ Kp,
        const __half* __restrict__ Vt, const int* __restrict__ mask,
        float* __restrict__ Ctx)
{
    __shared__ __half KV[2][128 * KLD];

    const int tid = threadIdx.x;
    const int lane = tid & 31, wid = tid >> 5;
    const int g = lane >> 2, tig = lane & 3;
    const int b = blockIdx.y / HEADS, h = blockIdx.y % HEADS;
    const int q0 = blockIdx.x * 128;
    const int qb = wid * 32;

    const __half* kg = Kp + ((size_t)b * SEQ) * DMODEL + h * DK;
    const __half* vg = Vt + ((size_t)(b * DMODEL + h * DK)) * SEQ;
    const int* mg = mask + b * SEQ;

    // ---- stage Q (fp16, pre-scaled) through KV[0], lift A-frags ----
    {
        const __half* qg = Qp + ((size_t)(b * SEQ + q0)) * DMODEL + h * DK;
        #pragma unroll
        for (int i = 0; i < 8; i++) {
            const int L = tid + i * 128;
            const int r = L >> 3, c8 = (L & 7) * 8;
            *(uint4*)(KV[0] + r * KLD + c8) =
                *(const uint4*)(qg + (size_t)r * DMODEL + c8);
        }
    }
    __syncthreads();

    uint32_t qf[4][2][4];
    #pragma unroll
    for (int c = 0; c < 4; c++) {
        const int kk = 16 * c + 2 * tig;
        #pragma unroll
        for (int i = 0; i < 2; i++) {
            const int rb = qb + 16 * i;
            qf[c][i][0] = *(const uint32_t*)&KV[0][(rb + g) * KLD + kk];
            qf[c][i][1] = *(const uint32_t*)&KV[0][(rb + 8 + g) * KLD + kk];
            qf[c][i][2] = *(const uint32_t*)&KV[0][(rb + g) * KLD + kk + 8];
            qf[c][i][3] = *(const uint32_t*)&KV[0][(rb + 8 + g) * KLD + kk + 8];
        }
    }
    __syncthreads();

    // ---- hoisted prefetch addressing (loop-invariant) ----
    const int pr = tid >> 3;              // 0..15
    const int pc = (tid & 7) * 8;         // 0..56
    const __half* ksrc = kg + (size_t)pr * DMODEL + pc;
    const __half* vsrc = vg + (size_t)pr * SEQ + pc;
    const uint32_t dk0 =
        (uint32_t)__cvta_generic_to_shared(&KV[0][pr * KLD + pc]);

    float o[2][8][4] = {};
    float lacc[2][4] = {};               // ones-MMA row-sum accumulators
    const uint32_t ONE2 = 0x3C003C00u;   // half2(1.0, 1.0)
    const float NEGINF = __int_as_float(0xff800000);

    // prefetch tile 0 into buffer 0
    {
        const uint32_t dV = dk0 + 64 * KLD * 2;
        #pragma unroll
        for (int i = 0; i < 4; i++) {
            cpa16r(dk0 + i * (16 * KLD * 2), ksrc + (size_t)i * 16 * DMODEL);
            cpa16r(dV + i * (16 * KLD * 2), vsrc + (size_t)i * 16 * SEQ);
        }
        CPA_COMMIT();
        ksrc += (size_t)64 * DMODEL;
        vsrc += 64;
    }

    for (int kt = 0; kt < NT; kt++) {
        const int cur = kt & 1;
        const __half* Ks = KV[cur];
        const __half* Vs = KV[cur] + 64 * KLD;

        // mask word for the all-ones test (L2-hot; issued early)
        const int mv = __ldg(mg + kt * 64 + (tid & 63));

        if (kt + 1 < NT) {
            const uint32_t dK = dk0 + (cur ^ 1) * BUFB;
            const uint32_t dV = dK + 64 * KLD * 2;
            #pragma unroll
            for (int i = 0; i < 4; i++) {
                cpa16r(dK + i * (16 * KLD * 2), ksrc + (size_t)i * 16 * DMODEL);
                cpa16r(dV + i * (16 * KLD * 2), vsrc + (size_t)i * 16 * SEQ);
            }
            CPA_COMMIT();
            ksrc += (size_t)64 * DMODEL;
            vsrc += 64;
            CPA_WAIT1();
        } else {
            CPA_WAIT0();
        }
        const int allone = __syncthreads_and(mv != 0);

        // ---- S = Q K^T (exp2-domain scores) ----
        float s[2][8][4] = {};
        #pragma unroll
        for (int c = 0; c < 4; c++) {
            const int kk = 16 * c + 2 * tig;
            #pragma unroll
            for (int j = 0; j < 8; j++) {
                const int rn = (j * 8 + g) * KLD + kk;
                uint32_t b0 = *(const uint32_t*)&Ks[rn];
                uint32_t b1 = *(const uint32_t*)&Ks[rn + 8];
                mma16(s[0][j], qf[c][0], b0, b1);
                mma16(s[1][j], qf[c][1], b0, b1);
            }
        }

        // ---- mask (rare path): poison scores with -inf ----
        if (!allone) {
            #pragma unroll
            for (int j = 0; j < 8; j++) {
                int2 mi = __ldg((const int2*)(mg + kt * 64 + j * 8 + 2 * tig));
                if (!mi.x) {
                    s[0][j][0] = NEGINF; s[0][j][2] = NEGINF;
                    s[1][j][0] = NEGINF; s[1][j][2] = NEGINF;
                }
                if (!mi.y) {
                    s[0][j][1] = NEGINF; s[0][j][3] = NEGINF;
                    s[1][j][1] = NEGINF; s[1][j][3] = NEGINF;
                }
            }
        }

        // ---- p = exp2(s) in f16x2; the cvt result IS the P fragment ----
        uint32_t pa[2][8][2];
        #pragma unroll
        for (int j = 0; j < 8; j++) {
            pa[0][j][0] = ex2h2(packh2(s[0][j][0], s[0][j][1]));
            pa[0][j][1] = ex2h2(packh2(s[0][j][2], s[0][j][3]));
            pa[1][j][0] = ex2h2(packh2(s[1][j][0], s[1][j][1]));
            pa[1][j][1] = ex2h2(packh2(s[1][j][2], s[1][j][3]));
        }

        // ---- O += P V^T ; l += P·1 (ones-MMA, no smem) ----
        #pragma unroll
        for (int m = 0; m < 4; m++) {
            uint32_t av0[4] = { pa[0][2 * m][0], pa[0][2 * m][1],
                                pa[0][2 * m + 1][0], pa[0][2 * m + 1][1] };
            uint32_t av1[4] = { pa[1][2 * m][0], pa[1][2 * m][1],
                                pa[1][2 * m + 1][0], pa[1][2 * m + 1][1] };
            const int kk = 16 * m + 2 * tig;
            #pragma unroll
            for (int j = 0; j < 8; j++) {
                const int rn = (j * 8 + g) * KLD + kk;
                uint32_t b0 = *(const uint32_t*)&Vs[rn];
                uint32_t b1 = *(const uint32_t*)&Vs[rn + 8];
                mma16(o[0][j], av0, b0, b1);
                mma16(o[1][j], av1, b0, b1);
            }
            mma16(lacc[0], av0, ONE2, ONE2);
            mma16(lacc[1], av1, ONE2, ONE2);
        }
        __syncthreads();
    }

    // ---- finalize: l already fully reduced by the ones-MMA ----
    const float inv[2][2] = { {1.f / lacc[0][0], 1.f / lacc[0][2]},
                              {1.f / lacc[1][0], 1.f / lacc[1][2]} };

    #pragma unroll
    for (int i = 0; i < 2; i++) {
        float* cg = Ctx + ((size_t)(b * SEQ + q0 + qb + 16 * i)) * DMODEL + h * DK;
        #pragma unroll
        for (int j = 0; j < 8; j++) {
            const int col = j * 8 + 2 * tig;
            *(float2*)(cg + (size_t)g * DMODEL + col) =
                make_float2(o[i][j][0] * inv[i][0], o[i][j][1] * inv[i][0]);
            *(float2*)(cg + (size_t)(8 + g) * DMODEL + col) =
                make_float2(o[i][j][2] * inv[i][1], o[i][j][3] * inv[i][1]);
        }
    }
}

// ---------------------------------------------------------------------------
// Launcher.  Inputs: q, k, v, Wq, bq, Wk, bk, Wv, bv, Wo, bo, mask
// ---------------------------------------------------------------------------
extern "C" void kernel_launch(void* const* d_in, const int* in_sizes, int n_in,
                              void* d_out, int out_size)
{
    const float* q    = (const float*)d_in[0];
    const float* k    = (const float*)d_in[1];
    const float* v    = (const float*)d_in[2];
    const float* Wq   = (const float*)d_in[3];
    const float* bq   = (const float*)d_in[4];
    const float* Wk   = (const float*)d_in[5];
    const float* bk   = (const float*)d_in[6];
    const float* Wv   = (const float*)d_in[7];
    const float* bv   = (const float*)d_in[8];
    const float* Wo   = (const float*)d_in[9];
    const float* bo   = (const float*)d_in[10];
    const int*   mask = (const int*)d_in[11];
    float* out = (float*)d_out;

    __half *Qp, *Kp, *Vt;
    float *Ctx;
    cudaGetSymbolAddress((void**)&Qp,  g_Qp);
    cudaGetSymbolAddress((void**)&Kp,  g_Kp);
    cudaGetSymbolAddress((void**)&Vt,  g_Vt);
    cudaGetSymbolAddress((void**)&Ctx, g_Ctx);

    dim3 ggrid(DMODEL / GBN, MROWS / GBM);   // (6, 64)
    dim3 gblk(256);

    // Q scale folds 1/sqrt(dk) AND log2(e): scores emerge in exp2 domain.
    const float qscale = 0.125f * 1.44269504088896340736f;

    gemm_tc<__half, 0><<<ggrid, gblk>>>(q, Wq, bq, Qp, MROWS, DMODEL, DMODEL, qscale);
    gemm_tc<__half, 0><<<ggrid, gblk>>>(k, Wk, bk, Kp, MROWS, DMODEL, DMODEL, 1.0f);
    gemm_tc<__half, 1><<<ggrid, gblk>>>(v, Wv, bv, Vt, MROWS, DMODEL, DMODEL, 1.0f);

    dim3 agrid(SEQ / 128, BS * HEADS);       // (32, 24)
    attn_tc<<<agrid, 128>>>(Qp, Kp, Vt, mask, Ctx);

    gemm_tc<float, 0><<<ggrid, gblk>>>(Ctx, Wo, bo, out, MROWS, DMODEL, DMODEL, 1.0f);
}